// round 2
// baseline (speedup 1.0000x reference)
#include <cuda_runtime.h>

#define NNODES 100000
#define NEDGES 600000
#define FIN 128
#define FOUT 64

// ---------------- scratch (static device allocations; no cudaMalloc) --------
__device__ float g_deg[NNODES];
__device__ float g_dis[NNODES];      // rsqrt(deg+1)
__device__ float g_invdeg[NNODES];   // 1/(deg+1)
__device__ float g_xp[(size_t)NNODES * FOUT];   // x @ W_sn
__device__ float g_inv_sigma;
__device__ int   g_is64;             // 1 if edge_index is int64, 0 if int32

__device__ __forceinline__ int edge_at(const void* ei, long long i) {
    // branch on uniform flag; must NOT speculate the int64 load (buffer may be
    // only half the size if data is int32)
    if (g_is64) return (int)((const long long*)ei)[i];
    return ((const int*)ei)[i];
}

// ---------------- kernel 0: dtype detect + spectral norm --------------------
__global__ void k_prep(const void* ei, const float* __restrict__ W,
                       const float* __restrict__ u) {
    __shared__ float sv[64];
    __shared__ float red[128];
    int t = threadIdx.x;  // 128 threads

    if (t == 0) {
        // int64 data viewed as int32: every odd word is the (zero) high half,
        // since all indices are in [0, 1e5). Genuine int32 data has ~0 chance
        // of 128 consecutive zero odd words.
        const int* e32 = (const int*)ei;
        int is64 = 1;
        for (int i = 1; i < 256; i += 2)
            if (e32[i] != 0) { is64 = 0; break; }
        g_is64 = is64;
    }

    // v_t = W^T u  (thread t<64 owns column t)
    float vt = 0.f;
    if (t < 64) {
        #pragma unroll 8
        for (int i = 0; i < FIN; i++) vt += W[i * FOUT + t] * u[i];
    }
    red[t] = (t < 64) ? vt * vt : 0.f;
    __syncthreads();
    for (int s = 64; s > 0; s >>= 1) {
        if (t < s) red[t] += red[t + s];
        __syncthreads();
    }
    float nv = sqrtf(red[0]);
    __syncthreads();
    if (t < 64) sv[t] = vt / (nv + 1e-12f);
    __syncthreads();

    // Wv (thread t owns row t of W, t in [0,128))
    float wv = 0.f;
    #pragma unroll 8
    for (int j = 0; j < FOUT; j++) wv += W[t * FOUT + j] * sv[j];
    red[t] = wv * wv;
    __syncthreads();
    for (int s = 64; s > 0; s >>= 1) {
        if (t < s) red[t] += red[t + s];
        __syncthreads();
    }
    if (t == 0) {
        float s2 = red[0];
        float n = sqrtf(s2);
        // sigma = u2 . (Wv) where u2 = Wv/(||Wv||+eps)  =>  sigma = s2/(n+eps)
        float sigma = s2 / (n + 1e-12f);
        g_inv_sigma = 1.0f / sigma;
    }
}

// ---------------- kernel 1: zero degree array --------------------------------
__global__ void k_zero() {
    int i = blockIdx.x * blockDim.x + threadIdx.x;
    if (i < NNODES) g_deg[i] = 0.f;
}

// ---------------- kernel 2: degree accumulation ------------------------------
__global__ void k_deg(const void* ei, const float* __restrict__ ew) {
    int e = blockIdx.x * blockDim.x + threadIdx.x;
    if (e >= NEDGES) return;
    int col = edge_at(ei, (long long)NEDGES + e);
    float w = 1.f / (1.f + __expf(-ew[e]));
    atomicAdd(&g_deg[col], w);
}

// ---------------- kernel 3: dis / invdeg -------------------------------------
__global__ void k_dis() {
    int i = blockIdx.x * blockDim.x + threadIdx.x;
    if (i >= NNODES) return;
    float d = g_deg[i] + 1.f;   // +1 self loop
    g_dis[i] = rsqrtf(d);
    g_invdeg[i] = 1.f / d;
}

// ---------------- kernel 4: xp = x @ (W/sigma); out = xp*invdeg + bias -------
__global__ __launch_bounds__(256)
void k_gemm(const float* __restrict__ x, const float* __restrict__ W,
            const float* __restrict__ bias, float* __restrict__ out) {
    __shared__ float Ws[FIN * FOUT];  // 32 KB
    float inv_sigma = g_inv_sigma;
    for (int i = threadIdx.x; i < FIN * FOUT; i += 256)
        Ws[i] = W[i] * inv_sigma;
    __syncthreads();

    int row = blockIdx.x * 256 + threadIdx.x;
    if (row >= NNODES) return;

    float4 acc[16];
    #pragma unroll
    for (int j = 0; j < 16; j++) acc[j] = make_float4(0.f, 0.f, 0.f, 0.f);

    const float4* xr = (const float4*)(x + (size_t)row * FIN);
    for (int k4 = 0; k4 < FIN / 4; ++k4) {
        float4 xv = xr[k4];
        const float4* w0 = (const float4*)&Ws[(k4 * 4 + 0) * FOUT];
        const float4* w1 = (const float4*)&Ws[(k4 * 4 + 1) * FOUT];
        const float4* w2 = (const float4*)&Ws[(k4 * 4 + 2) * FOUT];
        const float4* w3 = (const float4*)&Ws[(k4 * 4 + 3) * FOUT];
        #pragma unroll
        for (int j = 0; j < 16; j++) {
            float4 a = acc[j];
            float4 b0 = w0[j], b1 = w1[j], b2 = w2[j], b3 = w3[j];
            a.x = fmaf(xv.x, b0.x, a.x); a.y = fmaf(xv.x, b0.y, a.y);
            a.z = fmaf(xv.x, b0.z, a.z); a.w = fmaf(xv.x, b0.w, a.w);
            a.x = fmaf(xv.y, b1.x, a.x); a.y = fmaf(xv.y, b1.y, a.y);
            a.z = fmaf(xv.y, b1.z, a.z); a.w = fmaf(xv.y, b1.w, a.w);
            a.x = fmaf(xv.z, b2.x, a.x); a.y = fmaf(xv.z, b2.y, a.y);
            a.z = fmaf(xv.z, b2.z, a.z); a.w = fmaf(xv.z, b2.w, a.w);
            a.x = fmaf(xv.w, b3.x, a.x); a.y = fmaf(xv.w, b3.y, a.y);
            a.z = fmaf(xv.w, b3.z, a.z); a.w = fmaf(xv.w, b3.w, a.w);
            acc[j] = a;
        }
    }

    float invdeg = g_invdeg[row];
    float4* xpr = (float4*)&g_xp[(size_t)row * FOUT];
    float4* outr = (float4*)(out + (size_t)row * FOUT);
    const float4* b4 = (const float4*)bias;
    #pragma unroll
    for (int j = 0; j < 16; j++) {
        float4 a = acc[j];
        float4 bb = b4[j];
        xpr[j] = a;
        float4 o;
        o.x = fmaf(a.x, invdeg, bb.x);
        o.y = fmaf(a.y, invdeg, bb.y);
        o.z = fmaf(a.z, invdeg, bb.z);
        o.w = fmaf(a.w, invdeg, bb.w);
        outr[j] = o;
    }
}

// ---------------- kernel 5: edge scatter (16 lanes per edge) ------------------
__global__ __launch_bounds__(256)
void k_scatter(const void* ei, const float* __restrict__ ew,
               float* __restrict__ out) {
    long long gt = (long long)blockIdx.x * blockDim.x + threadIdx.x;
    int lane = (int)(gt & 15);
    long long e = gt >> 4;
    if (e >= NEDGES) return;

    int row = edge_at(ei, e);
    int col = edge_at(ei, (long long)NEDGES + e);
    float w = 1.f / (1.f + __expf(-ew[e]));
    float ne = g_dis[row] * w * g_dis[col];

    float4 m = ((const float4*)&g_xp[(size_t)row * FOUT])[lane];
    float* p = out + (size_t)col * FOUT + lane * 4;
    asm volatile("red.global.add.v4.f32 [%0], {%1, %2, %3, %4};"
                 :: "l"(p), "f"(m.x * ne), "f"(m.y * ne),
                    "f"(m.z * ne), "f"(m.w * ne)
                 : "memory");
}

// ---------------- launcher ----------------------------------------------------
extern "C" void kernel_launch(void* const* d_in, const int* in_sizes, int n_in,
                              void* d_out, int out_size) {
    const float* x    = (const float*)d_in[0];
    const void*  ei   = d_in[1];
    const float* W    = (const float*)d_in[2];
    const float* bias = (const float*)d_in[3];
    const float* ew   = (const float*)d_in[4];
    const float* u    = (const float*)d_in[5];
    float* out = (float*)d_out;

    k_prep<<<1, 128>>>(ei, W, u);
    k_zero<<<(NNODES + 255) / 256, 256>>>();
    k_deg<<<(NEDGES + 255) / 256, 256>>>(ei, ew);
    k_dis<<<(NNODES + 255) / 256, 256>>>();
    k_gemm<<<(NNODES + 255) / 256, 256>>>(x, W, bias, out);
    k_scatter<<<(NEDGES * 16 + 255) / 256, 256>>>(ei, ew, out);
}